// round 2
// baseline (speedup 1.0000x reference)
#include <cuda_runtime.h>
#include <cuda_bf16.h>

#define NN  16384
#define DD  32
#define INPD 256
#define UU  128
#define RR  8
#define ENTT 8

// ---------------- scratch (device globals: no allocation allowed) ----------------
__device__ float g_center[NN * UU];            // (N, U)
__device__ float g_qr[NN * RR * UU];           // (N, R*U)  per-node per-relation query
__device__ float g_s[NN * RR * UU];            // (N, R*U)  attn-weighted neighbor sums
__device__ float g_kT[UU * UU];                // k_w^T
__device__ float g_relT[RR * UU * UU];         // rel_w[r]^T
__device__ float g_qk[UU * UU];                // q_w @ k_w^T
__device__ float g_vf[UU * UU];                // v_w @ fc_w
__device__ float g_Bk2[UU * RR * UU];          // (U, R*U): col r*128+a = (1/U) * qk @ rel_w[r]^T
__device__ float g_Bv2[RR * UU * UU];          // (R*U, U): rel_w[r] @ vf
__device__ int   g_cnt[ENTT];
__device__ int   g_lists[ENTT * NN];

// ---------------- transpose k_w and rel_w[r] ----------------
__global__ void transpose_kernel(const float* __restrict__ k_w,
                                 const float* __restrict__ rel_w)
{
    int m = blockIdx.z;
    const float* src = (m == 0) ? k_w : (rel_w + (m - 1) * UU * UU);
    float* dst = (m == 0) ? g_kT : (g_relT + (m - 1) * UU * UU);
    __shared__ float t[32][33];
    int tx = threadIdx.x, ty = threadIdx.y;   // block (32, 8)
    int x = blockIdx.x * 32 + tx;
    int y0 = blockIdx.y * 32;
#pragma unroll
    for (int i = 0; i < 4; i++)
        t[ty + 8 * i][tx] = src[(y0 + ty + 8 * i) * UU + x];
    __syncthreads();
    int x2 = blockIdx.y * 32 + tx;
    int y2 = blockIdx.x * 32;
#pragma unroll
    for (int i = 0; i < 4; i++)
        dst[(y2 + ty + 8 * i) * UU + x2] = t[tx][ty + 8 * i];
}

// ---------------- entity partition ----------------
__global__ void zero_cnt_kernel() {
    if (threadIdx.x < ENTT) g_cnt[threadIdx.x] = 0;
}
__global__ void partition_kernel(const int* __restrict__ pe) {
    int n = blockIdx.x * blockDim.x + threadIdx.x;
    if (n < NN) {
        int e = pe[n];
        int pos = atomicAdd(&g_cnt[e], 1);
        g_lists[e * NN + pos] = n;
    }
}

// ---------------- generic 64x128x32 tiled fp32 GEMM ----------------
// C[row, n0+col] = alpha * sum_k A[row, k] * B[k, n0+col] (+bias, relu, +addsrc)
// Optional row gather via rowlists/cnts (per blockIdx.z).
__global__ __launch_bounds__(256) void gemm_tile(
    const float* __restrict__ A, int lda, long sAz,
    const float* __restrict__ B, int ldb, long sBz,
    float* __restrict__ C, int ldc, long sCz,
    int M, int K,
    const int* __restrict__ rowlists, const int* __restrict__ cnts,
    const float* __restrict__ bias, const float* __restrict__ addsrc,
    int do_relu, float alpha)
{
    __shared__ float As[64][33];
    __shared__ float Bs[32][128];
    __shared__ int rowidx[64];

    int z = blockIdx.z;
    A += z * sAz; B += z * sBz; C += z * sCz;
    int m0 = blockIdx.x * 64;
    int n0 = blockIdx.y * 128;
    int rows = rowlists ? cnts[z] : M;
    if (m0 >= rows) return;
    const int* rl = rowlists ? (rowlists + z * NN) : nullptr;

    int tid = threadIdx.x;
    if (tid < 64) {
        int g = m0 + tid;
        rowidx[tid] = (g < rows) ? (rl ? rl[g] : g) : -1;
    }
    __syncthreads();

    int tx = tid & 15, ty = tid >> 4;
    float acc[4][8];
#pragma unroll
    for (int i = 0; i < 4; i++)
#pragma unroll
        for (int j = 0; j < 8; j++) acc[i][j] = 0.f;

    for (int kt = 0; kt < K; kt += 32) {
#pragma unroll
        for (int j = 0; j < 8; j++) {          // A: 64x32
            int lin = tid + j * 256;
            int lr = lin >> 5, lc = lin & 31;
            int ar = rowidx[lr];
            As[lr][lc] = (ar >= 0) ? A[ar * lda + kt + lc] : 0.f;
        }
#pragma unroll
        for (int j = 0; j < 16; j++) {         // B: 32x128
            int lin = tid + j * 256;
            int br = lin >> 7, bc = lin & 127;
            Bs[br][bc] = B[(kt + br) * ldb + n0 + bc];
        }
        __syncthreads();
#pragma unroll
        for (int kk = 0; kk < 32; kk++) {
            float bv[8];
#pragma unroll
            for (int j = 0; j < 8; j++) bv[j] = Bs[kk][tx + 16 * j];
#pragma unroll
            for (int i = 0; i < 4; i++) {
                float av = As[ty * 4 + i][kk];
#pragma unroll
                for (int j = 0; j < 8; j++) acc[i][j] += av * bv[j];
            }
        }
        __syncthreads();
    }

#pragma unroll
    for (int i = 0; i < 4; i++) {
        int cr = rowidx[ty * 4 + i];
        if (cr < 0) continue;
#pragma unroll
        for (int j = 0; j < 8; j++) {
            int col = n0 + tx + 16 * j;
            float v = acc[i][j] * alpha;
            if (bias) v += bias[col];
            if (do_relu) v = fmaxf(v, 0.f);
            if (addsrc) v += addsrc[cr * ldc + col];
            C[cr * ldc + col] = v;
        }
    }
}

// ---------------- fused gather / score / softmax / weighted-scatter ----------------
__global__ __launch_bounds__(128) void edge_kernel(const int* __restrict__ adjacency,
                                                   const int* __restrict__ relation)
{
    __shared__ float xs[DD][UU];      // gathered neighbor embeddings
    __shared__ float aw[RR][DD];      // per-relation masked attention
    __shared__ float scores[DD];
    __shared__ int adjs[DD];
    __shared__ int rels[DD];

    int n = blockIdx.x;
    int tid = threadIdx.x, lane = tid & 31, w = tid >> 5;

    if (tid < DD) {
        adjs[tid] = adjacency[n * DD + tid];
        rels[tid] = relation[n * DD + tid];
    }
    __syncthreads();

    // gather x: warp w loads rows d = w*8 .. w*8+7 (float4, coalesced)
#pragma unroll
    for (int i = 0; i < 8; i++) {
        int d = w * 8 + i;
        int idx = adjs[d];
        float4 v = (idx > 0)
            ? reinterpret_cast<const float4*>(g_center + (idx - 1) * UU)[lane]
            : make_float4(0.f, 0.f, 0.f, 0.f);
        reinterpret_cast<float4*>(&xs[d][0])[lane] = v;
    }
    __syncwarp();

    // scores[d] = qr[n, rel[d]] . x[d]  (1/U already folded into g_Bk2)
    const float* qbase = g_qr + n * (RR * UU);
#pragma unroll
    for (int i = 0; i < 8; i++) {
        int d = w * 8 + i;
        int r = rels[d];
        const float* q = qbase + r * UU;
        float s = 0.f;
#pragma unroll
        for (int k2 = 0; k2 < 4; k2++) {
            int c = lane + 32 * k2;
            s += q[c] * xs[d][c];
        }
#pragma unroll
        for (int off = 16; off > 0; off >>= 1) s += __shfl_xor_sync(0xffffffffu, s, off);
        if (lane == 0) scores[d] = (r == 0) ? -1e9f : s;
    }
    __syncthreads();

    // softmax over D=32 (warp 0), then per-relation masked attention
    if (w == 0) {
        float v = scores[lane];
        float m = v;
#pragma unroll
        for (int off = 16; off > 0; off >>= 1) m = fmaxf(m, __shfl_xor_sync(0xffffffffu, m, off));
        float e = __expf(v - m);
        float sum = e;
#pragma unroll
        for (int off = 16; off > 0; off >>= 1) sum += __shfl_xor_sync(0xffffffffu, sum, off);
        float a = e / sum;
        int r = rels[lane];
#pragma unroll
        for (int rr = 0; rr < RR; rr++) aw[rr][lane] = (r == rr) ? a : 0.f;
    }
    __syncthreads();

    // s[n, r, :] = sum_d aw[r][d] * x[d, :]
    float acc[RR];
#pragma unroll
    for (int r = 0; r < RR; r++) acc[r] = 0.f;
#pragma unroll
    for (int d = 0; d < DD; d++) {
        float x = xs[d][tid];
#pragma unroll
        for (int r = 0; r < RR; r++) acc[r] += aw[r][d] * x;
    }
    float* sp = g_s + n * (RR * UU) + tid;
#pragma unroll
    for (int r = 0; r < RR; r++) sp[r * UU] = acc[r];
}

// ---------------- launch ----------------
extern "C" void kernel_launch(void* const* d_in, const int* in_sizes, int n_in,
                              void* d_out, int out_size)
{
    const float* node_state = (const float*)d_in[0];
    const int*   adjacency  = (const int*)d_in[1];
    const int*   point_enc  = (const int*)d_in[2];
    const int*   relation   = (const int*)d_in[3];
    const float* pe_w       = (const float*)d_in[4];
    const float* rel_w      = (const float*)d_in[5];
    const float* q_w        = (const float*)d_in[6];
    const float* k_w        = (const float*)d_in[7];
    const float* v_w        = (const float*)d_in[8];
    const float* fc_w       = (const float*)d_in[9];
    const float* fc_b       = (const float*)d_in[10];
    float* out = (float*)d_out;

    float *p_center, *p_qr, *p_s, *p_kT, *p_relT, *p_qk, *p_vf, *p_Bk2, *p_Bv2;
    int *p_cnt, *p_lists;
    cudaGetSymbolAddress((void**)&p_center, g_center);
    cudaGetSymbolAddress((void**)&p_qr,     g_qr);
    cudaGetSymbolAddress((void**)&p_s,      g_s);
    cudaGetSymbolAddress((void**)&p_kT,     g_kT);
    cudaGetSymbolAddress((void**)&p_relT,   g_relT);
    cudaGetSymbolAddress((void**)&p_qk,     g_qk);
    cudaGetSymbolAddress((void**)&p_vf,     g_vf);
    cudaGetSymbolAddress((void**)&p_Bk2,    g_Bk2);
    cudaGetSymbolAddress((void**)&p_Bv2,    g_Bv2);
    cudaGetSymbolAddress((void**)&p_cnt,    g_cnt);
    cudaGetSymbolAddress((void**)&p_lists,  g_lists);

    // 1. transposes of k_w and rel_w[r]
    transpose_kernel<<<dim3(4, 4, 9), dim3(32, 8)>>>(k_w, rel_w);

    // 2. qk = q_w @ k_w^T ; vf = v_w @ fc_w
    gemm_tile<<<dim3(2, 1, 1), 256>>>(q_w, 128, 0, p_kT, 128, 0, p_qk, 128, 0,
                                      128, 128, nullptr, nullptr, nullptr, nullptr, 0, 1.f);
    gemm_tile<<<dim3(2, 1, 1), 256>>>(v_w, 128, 0, fc_w, 128, 0, p_vf, 128, 0,
                                      128, 128, nullptr, nullptr, nullptr, nullptr, 0, 1.f);

    // 3. Bk2[:, r*128+a] = (1/U) * qk @ rel_w[r]^T ; Bv2[r*128+a, :] = rel_w[r] @ vf
    gemm_tile<<<dim3(2, 1, 8), 256>>>(p_qk, 128, 0, p_relT, 128, (long)UU * UU,
                                      p_Bk2, 1024, 128,
                                      128, 128, nullptr, nullptr, nullptr, nullptr, 0, 1.f / 128.f);
    gemm_tile<<<dim3(2, 1, 8), 256>>>(rel_w, 128, (long)UU * UU, p_vf, 128, 0,
                                      p_Bv2, 128, (long)UU * UU,
                                      128, 128, nullptr, nullptr, nullptr, nullptr, 0, 1.f);

    // 4. entity partition
    zero_cnt_kernel<<<1, 32>>>();
    partition_kernel<<<NN / 256, 256>>>(point_enc);

    // 5. center[n] = node_state[n] @ point_enc_w[point_enc[n]]   (gathered GEMM per entity)
    gemm_tile<<<dim3(256, 1, 8), 256>>>(node_state, INPD, 0,
                                        pe_w, 128, (long)INPD * UU,
                                        p_center, 128, 0,
                                        0, INPD, p_lists, p_cnt, nullptr, nullptr, 0, 1.f);

    // 6. qr = center @ Bk2   (N x 1024, K=128)
    gemm_tile<<<dim3(256, 8, 1), 256>>>(p_center, 128, 0, p_Bk2, 1024, 0,
                                        p_qr, 1024, 0,
                                        NN, 128, nullptr, nullptr, nullptr, nullptr, 0, 1.f);

    // 7. fused gather / scores / softmax / per-relation weighted sums
    edge_kernel<<<NN, 128>>>(adjacency, relation);

    // 8. out = center + relu(s @ Bv2 + fc_b)   (N x 128, K=1024)
    gemm_tile<<<dim3(256, 1, 1), 256>>>(p_s, 1024, 0, p_Bv2, 128, 0,
                                        out, 128, 0,
                                        NN, 1024, nullptr, nullptr, fc_b, p_center, 1, 1.f);
}